// round 13
// baseline (speedup 1.0000x reference)
#include <cuda_runtime.h>
#include <cuda_fp16.h>
#include <cstdint>

#define NHEAD  8
#define NTOK   49
#define BWIN   1024
#define MROWS  50176
#define NQ     12845056           // 16*56*56*256

__device__ __half g_qh[NQ];               // fp16 query (GEMM A)
__device__ __half g_aoh[MROWS * 256];     // fp16 attn output
__device__ __half g_whq[768 * 256];       // w_qkv^T [n][k] fp16
__device__ __half g_whp[256 * 256];       // w_proj^T [n][k] fp16
__device__ __half g_qa[BWIN * NHEAD * NTOK * 32];   // attn Q (pre-scaled)
__device__ __half g_ka[BWIN * NHEAD * NTOK * 32];   // attn K
__device__ __half g_vt[BWIN * NHEAD * 32 * 64];     // attn V transposed [d][tok64]
__device__ unsigned g_tblw[4 * 8 * 64 * 36];        // fused bias+mask, half2 words

// fp16 m16n8k16
__device__ __forceinline__ void mma16(float* c, const unsigned* a, const unsigned* b) {
    asm volatile(
        "mma.sync.aligned.m16n8k16.row.col.f32.f16.f16.f32 "
        "{%0,%1,%2,%3},{%4,%5,%6,%7},{%8,%9},{%0,%1,%2,%3};"
        : "+f"(c[0]), "+f"(c[1]), "+f"(c[2]), "+f"(c[3])
        : "r"(a[0]), "r"(a[1]), "r"(a[2]), "r"(a[3]), "r"(b[0]), "r"(b[1]));
}

__device__ __forceinline__ void cpa16(unsigned dst, const void* src) {
    asm volatile("cp.async.cg.shared.global [%0], [%1], 16;" :: "r"(dst), "l"(src));
}
__device__ __forceinline__ void cpa_commit() {
    asm volatile("cp.async.commit_group;");
}
template <int N>
__device__ __forceinline__ void cpa_wait() {
    asm volatile("cp.async.wait_group %0;" :: "n"(N));
}

// ============================================================
// Pre-pass A: query fp32 -> fp16
// ============================================================
__global__ void __launch_bounds__(256) conv_q(const float4* __restrict__ q)
{
    int i = blockIdx.x * 256 + threadIdx.x;
    float4 v = q[i];
    half2 lo = __floats2half2_rn(v.x, v.y);
    half2 hi = __floats2half2_rn(v.z, v.w);
    uint2 pk;
    pk.x = *(unsigned*)&lo;
    pk.y = *(unsigned*)&hi;
    ((uint2*)g_qh)[i] = pk;
}

// ============================================================
// Pre-pass B: transpose + fp16 both weights
// ============================================================
__global__ void __launch_bounds__(256) conv_w(
    const float* __restrict__ w1, const float* __restrict__ w2)
{
    int i = blockIdx.x * 256 + threadIdx.x;
    if (i < 768 * 256) {
        int n = i >> 8, k = i & 255;
        g_whq[i] = __float2half_rn(w1[k * 768 + n]);
    } else {
        int j = i - 768 * 256;
        int n = j >> 8, k = j & 255;
        g_whp[j] = __float2half_rn(w2[k * 256 + n]);
    }
}

// ============================================================
// Pre-pass C: fused bias+mask table (4 win-types x 8 heads),
// half2 words laid out exactly like the P fragment (na*4+tg).
// ============================================================
__device__ __forceinline__ int cnt_of(int type, int tok) {
    int iy = tok / 7, ix = tok - iy * 7;
    int ry = (type & 2) ? (iy < 4 ? 1 : 2) : 0;
    int rx = (type & 1) ? (ix < 4 ? 1 : 2) : 0;
    return ry * 3 + rx;
}
__global__ void __launch_bounds__(256) tbl_build(const float* __restrict__ rbt)
{
    int idx = blockIdx.x * 256 + threadIdx.x;      // < 4*8*64*36
    int w = idx % 36;
    int row = (idx / 36) & 63;
    int h = (idx / 2304) & 7;
    int type = idx / 18432;
    int na = w >> 2, tg = w & 3;
    float v[2];
#pragma unroll
    for (int e = 0; e < 2; e++) {
        int col = na * 8 + 2 * tg + e;
        float val = -60000.f;
        if (row < 49 && col < 49) {
            int iy = row / 7, ix = row - iy * 7;
            int jy = col / 7, jx = col - jy * 7;
            val = rbt[((iy - jy + 6) * 13 + (ix - jx + 6)) * 8 + h];
            if (cnt_of(type, row) != cnt_of(type, col)) val -= 100.f;
        }
        v[e] = val;
    }
    half2 p = __floats2half2_rn(v[0], v[1]);
    g_tblw[idx] = *(unsigned*)&p;
}

// ============================================================
// Pre-pass D: zero g_vt token pads 48-63 (qkv rewrites tok 48)
// ============================================================
__global__ void __launch_bounds__(256) zero_vt(void)
{
    int i = blockIdx.x * 256 + threadIdx.x;        // < 8192*32*2
    int row = i >> 1, part = i & 1;
    *(uint4*)(g_vt + row * 64 + 48 + part * 8) = make_uint4(0u, 0u, 0u, 0u);
}

// ============================================================
// FP16 GEMM: block 128x128, 8 warps, K-chunk 32, 3-stage cp.async.
// ============================================================
#define A_ST 2560
#define B_BASE 7680
#define SMEM_BYTES 61440

template <int MODE>
__global__ void __launch_bounds__(256) hgemm(
    const float* __restrict__ bias, float* __restrict__ out)
{
    extern __shared__ unsigned sw[];
    __shared__ int rsrc[128];

    const int tid = threadIdx.x;
    const int m0 = blockIdx.x * 128;
    const int n0 = blockIdx.y * 128;

    if (MODE == 0 && tid < 128) {
        int m = m0 + tid;
        int win = m / 49, n = m - win * 49;
        int b = win >> 6, wy = (win >> 3) & 7, wx = win & 7;
        int iy = n / 7, ix = n - iy * 7;
        int y = wy * 7 + iy + 3; if (y >= 56) y -= 56;
        int x = wx * 7 + ix + 3; if (x >= 56) x -= 56;
        rsrc[tid] = ((b * 56 + y) * 56 + x) * 256;
    }
    __syncthreads();

    const unsigned sbase = (unsigned)__cvta_generic_to_shared(sw);
    const __half* Ah = (MODE == 0) ? g_qh : g_aoh;
    const __half* Bh = (MODE == 0) ? g_whq : g_whp;

    int ar[2], ac[2];
#pragma unroll
    for (int t = 0; t < 2; t++) {
        int id = tid + t * 256;
        ar[t] = id >> 2;  ac[t] = id & 3;
    }

#define ISSUE(STG, K0)                                                        \
    {                                                                         \
        _Pragma("unroll") for (int t = 0; t < 2; t++)                         \
            cpa16(sbase + ((STG) * A_ST + ar[t] * 20 + ac[t] * 4) * 4,        \
                  (MODE == 0) ? (Ah + rsrc[ar[t]] + (K0) + ac[t] * 8)         \
                              : (Ah + (m0 + ar[t]) * 256 + (K0) + ac[t] * 8));\
        _Pragma("unroll") for (int t = 0; t < 2; t++)                         \
            cpa16(sbase + (B_BASE + (STG) * A_ST + ar[t] * 20 + ac[t] * 4) * 4,\
                  Bh + (n0 + ar[t]) * 256 + (K0) + ac[t] * 8);                \
    }

    float acc[4][4][4];
#pragma unroll
    for (int i = 0; i < 4; i++)
#pragma unroll
        for (int j = 0; j < 4; j++)
#pragma unroll
            for (int l = 0; l < 4; l++) acc[i][j][l] = 0.f;

    const int warp = tid >> 5, lane = tid & 31;
    const int g = lane >> 2, tg = lane & 3;
    const int wm = warp >> 2, wn = warp & 3;

    ISSUE(0, 0);  cpa_commit();
    ISSUE(1, 32); cpa_commit();
    cpa_wait<1>();
    __syncthreads();

    for (int it = 0; it < 8; it++) {
        const int stg = it - (it >= 6 ? 6 : (it >= 3 ? 3 : 0));
        const unsigned* As = sw + stg * A_ST;
        const unsigned* Bs = sw + B_BASE + stg * A_ST;

#pragma unroll
        for (int ka = 0; ka < 2; ka++) {
            unsigned a[4][4], bb[4][2];
            const int kw = ka * 8;
#pragma unroll
            for (int ma = 0; ma < 4; ma++) {
                int r = wm * 64 + ma * 16 + g;
                a[ma][0] = As[r * 20 + kw + tg];
                a[ma][1] = As[(r + 8) * 20 + kw + tg];
                a[ma][2] = As[r * 20 + kw + tg + 4];
                a[ma][3] = As[(r + 8) * 20 + kw + tg + 4];
            }
#pragma unroll
            for (int na = 0; na < 4; na++) {
                int nr = wn * 32 + na * 8 + g;
                bb[na][0] = Bs[nr * 20 + kw + tg];
                bb[na][1] = Bs[nr * 20 + kw + tg + 4];
            }
#pragma unroll
            for (int ma = 0; ma < 4; ma++)
#pragma unroll
                for (int na = 0; na < 4; na++) mma16(acc[ma][na], a[ma], bb[na]);
        }

        if (it + 2 < 8) {
            int ns = it + 2; ns -= (ns >= 6 ? 6 : (ns >= 3 ? 3 : 0));
            ISSUE(ns, (it + 2) * 32);
        }
        cpa_commit();
        cpa_wait<1>();
        __syncthreads();
    }
#undef ISSUE

    const float scale = 0.17677669529663687f;
#pragma unroll
    for (int ma = 0; ma < 4; ma++) {
#pragma unroll
        for (int rr = 0; rr < 2; rr++) {
            int r = m0 + wm * 64 + ma * 16 + g + rr * 8;
            int win = r / 49, n = r - win * 49;
            int obase = 0;
            if (MODE == 1) {
                int b = win >> 6, wy = (win >> 3) & 7, wx = win & 7;
                int iy = n / 7, ix = n - iy * 7;
                int y = wy * 7 + iy + 3; if (y >= 56) y -= 56;
                int x = wx * 7 + ix + 3; if (x >= 56) x -= 56;
                obase = ((b * 56 + y) * 56 + x) * 256;
            }
#pragma unroll
            for (int na = 0; na < 4; na++) {
                int c = n0 + wn * 32 + na * 8 + tg * 2;
                float v0 = acc[ma][na][rr * 2 + 0] + bias[c];
                float v1 = acc[ma][na][rr * 2 + 1] + bias[c + 1];
                if (MODE == 0) {
                    int part = c >> 8;
                    int hh = (c >> 5) & 7, d = c & 31;
                    if (part == 0) {
                        v0 *= scale; v1 *= scale;
                        *(half2*)(g_qa + (((win << 3) + hh) * 49 + n) * 32 + d) =
                            __floats2half2_rn(v0, v1);
                    } else if (part == 1) {
                        *(half2*)(g_ka + (((win << 3) + hh) * 49 + n) * 32 + d) =
                            __floats2half2_rn(v0, v1);
                    } else {
                        __half* vd = g_vt + ((((win << 3) + hh) * 32 + d) << 6) + n;
                        vd[0]  = __float2half_rn(v0);
                        vd[64] = __float2half_rn(v1);
                    }
                } else {
                    *(float2*)(out + obase + c) = make_float2(v0, v1);
                }
            }
        }
    }
}

// ============================================================
// FP16 attention: block = (window, head), 128 threads, 4 warps.
// ============================================================
__global__ void __launch_bounds__(128) attn_kernel(void)
{
    const int bx = blockIdx.x;
    const int win = bx >> 3, h = bx & 7;
    const int wy = (win >> 3) & 7, wx = win & 7;
    const int type = ((wy == 7) ? 2 : 0) | ((wx == 7) ? 1 : 0);

    __shared__ unsigned Qs[64 * 20];
    __shared__ unsigned Ks[56 * 20];
    __shared__ unsigned Vt[32 * 36];     // [d][tok64], stride 36 words
    __shared__ unsigned Pw[64 * 36];

    const int tid = threadIdx.x;
    const int warp = tid >> 5, lane = tid & 31;
    const int g = lane >> 2, tg = lane & 3;

    const int base = ((win * 8 + h) * 49) * 32;
    const __half* qp = g_qa + base;
    const __half* kp = g_ka + base;
    const __half* vp = g_vt + ((win * 8 + h) * 32) * 64;

    for (int i = tid; i < 196; i += 128) {
        int row = i >> 2, q = i & 3;
        *(uint4*)&Qs[row * 20 + q * 4] = ((const uint4*)qp)[i];
        *(uint4*)&Ks[row * 20 + q * 4] = ((const uint4*)kp)[i];
    }
    // zero K pad rows 49-55 (keeps S cols 49-55 finite)
    if (tid < 112) Ks[980 + tid] = 0u;
    if (tid < 28)  Ks[980 + 112 + tid] = 0u;
    // V: direct uint4 copies
    for (int i = tid; i < 256; i += 128) {
        int d = i >> 3, q = i & 7;
        *(uint4*)&Vt[d * 36 + q * 4] = ((const uint4*)vp)[i];
    }
    __syncthreads();

    const int r0 = warp * 16 + g;
    float invs[2];
    const unsigned* tbl = g_tblw + (type * 8 + h) * 2304;

    // ---- S = Q K^T (fp16 k16), fused table bias+mask+exp+rowsum ----
    {
        float acc[7][4];
#pragma unroll
        for (int na = 0; na < 7; na++)
#pragma unroll
            for (int l = 0; l < 4; l++) acc[na][l] = 0.f;

#pragma unroll
        for (int ka = 0; ka < 2; ka++) {
            const int kw = ka * 8;
            unsigned a[4];
            a[0] = Qs[r0 * 20 + kw + tg];
            a[1] = Qs[(r0 + 8) * 20 + kw + tg];
            a[2] = Qs[r0 * 20 + kw + tg + 4];
            a[3] = Qs[(r0 + 8) * 20 + kw + tg + 4];
#pragma unroll
            for (int na = 0; na < 7; na++) {
                int nr = na * 8 + g;
                unsigned b[2] = { Ks[nr * 20 + kw + tg],
                                  Ks[nr * 20 + kw + tg + 4] };
                mma16(acc[na], a, b);
            }
        }

#pragma unroll
        for (int half = 0; half < 2; half++) {
            int row = r0 + half * 8;
            const unsigned* tbr = tbl + row * 36;
            float esum = 0.f;
#pragma unroll
            for (int na = 0; na < 7; na++) {
                unsigned tw = __ldg(tbr + na * 4 + tg);
                half2 th = *(half2*)&tw;
                float ev0 = __expf(acc[na][half * 2 + 0] + __low2float(th));
                float ev1 = __expf(acc[na][half * 2 + 1] + __high2float(th));
                half2 p = __floats2half2_rn(ev0, ev1);
                Pw[row * 36 + na * 4 + tg] = *(unsigned*)&p;
                esum += ev0 + ev1;
            }
            Pw[row * 36 + 28 + tg] = 0u;           // cols 56-63 zero
            esum += __shfl_xor_sync(0xffffffffu, esum, 1);
            esum += __shfl_xor_sync(0xffffffffu, esum, 2);
            invs[half] = 1.f / esum;
        }
    }
    __syncwarp();

    // ---- O = P V (fp16 k16, k = 64 tokens incl. zero pad) ----
    {
        float o[4][4];
#pragma unroll
        for (int na = 0; na < 4; na++)
#pragma unroll
            for (int l = 0; l < 4; l++) o[na][l] = 0.f;

#pragma unroll
        for (int ka = 0; ka < 4; ka++) {
            const int kw = ka * 8;
            unsigned a[4];
            a[0] = Pw[r0 * 36 + kw + tg];
            a[1] = Pw[(r0 + 8) * 36 + kw + tg];
            a[2] = Pw[r0 * 36 + kw + tg + 4];
            a[3] = Pw[(r0 + 8) * 36 + kw + tg + 4];
#pragma unroll
            for (int na = 0; na < 4; na++) {
                int dr = na * 8 + g;
                unsigned b[2] = { Vt[dr * 36 + kw + tg],
                                  Vt[dr * 36 + kw + tg + 4] };
                mma16(o[na], a, b);
            }
        }

#pragma unroll
        for (int half = 0; half < 2; half++) {
            int row = r0 + half * 8;
            if (row < 49) {
                float s = invs[half];
                __half* op = g_aoh + (win * 49 + row) * 256 + h * 32;
#pragma unroll
                for (int na = 0; na < 4; na++) {
                    int col = na * 8 + 2 * tg;
                    *(half2*)(op + col) =
                        __floats2half2_rn(o[na][half * 2 + 0] * s,
                                          o[na][half * 2 + 1] * s);
                }
            }
        }
    }
}

// ============================================================
extern "C" void kernel_launch(void* const* d_in, const int* in_sizes, int n_in,
                              void* d_out, int out_size)
{
    const float* query  = (const float*)d_in[0];
    const float* w_qkv  = (const float*)d_in[1];
    const float* b_qkv  = (const float*)d_in[2];
    const float* w_proj = (const float*)d_in[3];
    const float* b_proj = (const float*)d_in[4];
    const float* rbt    = (const float*)d_in[5];
    float* out = (float*)d_out;

    static int attr_done = 0;
    if (!attr_done) {
        cudaFuncSetAttribute(hgemm<0>,
            cudaFuncAttributeMaxDynamicSharedMemorySize, SMEM_BYTES);
        cudaFuncSetAttribute(hgemm<1>,
            cudaFuncAttributeMaxDynamicSharedMemorySize, SMEM_BYTES);
        attr_done = 1;
    }

    conv_q<<<12544, 256>>>((const float4*)query);
    conv_w<<<1024, 256>>>(w_qkv, w_proj);
    tbl_build<<<288, 256>>>(rbt);
    zero_vt<<<2048, 256>>>();

    dim3 g1(392, 6);
    hgemm<0><<<g1, 256, SMEM_BYTES>>>(b_qkv, nullptr);

    attn_kernel<<<8192, 128>>>();

    dim3 g3(392, 2);
    hgemm<1><<<g3, 256, SMEM_BYTES>>>(b_proj, out);
}

// round 14
// speedup vs baseline: 1.5155x; 1.5155x over previous
#include <cuda_runtime.h>
#include <cuda_fp16.h>
#include <cstdint>

#define NHEAD  8
#define NTOK   49
#define BWIN   1024
#define MROWS  50176
#define NQ     12845056           // 16*56*56*256

__device__ __half g_qh[NQ];               // fp16 query (GEMM A)
__device__ __half g_aoh[MROWS * 256];     // fp16 attn output
__device__ __half g_whq[768 * 256];       // w_qkv^T [n][k] fp16
__device__ __half g_whp[256 * 256];       // w_proj^T [n][k] fp16
__device__ __half g_qa[BWIN * NHEAD * NTOK * 32];   // attn Q (pre-scaled)
__device__ __half g_ka[BWIN * NHEAD * NTOK * 32];   // attn K
__device__ __half g_va[BWIN * NHEAD * NTOK * 32];   // attn V (natural layout)
__device__ unsigned g_tblw[4 * 8 * 64 * 36];        // fused bias+mask, half2 words

// fp16 m16n8k16
__device__ __forceinline__ void mma16(float* c, const unsigned* a, const unsigned* b) {
    asm volatile(
        "mma.sync.aligned.m16n8k16.row.col.f32.f16.f16.f32 "
        "{%0,%1,%2,%3},{%4,%5,%6,%7},{%8,%9},{%0,%1,%2,%3};"
        : "+f"(c[0]), "+f"(c[1]), "+f"(c[2]), "+f"(c[3])
        : "r"(a[0]), "r"(a[1]), "r"(a[2]), "r"(a[3]), "r"(b[0]), "r"(b[1]));
}

__device__ __forceinline__ void cpa16(unsigned dst, const void* src) {
    asm volatile("cp.async.cg.shared.global [%0], [%1], 16;" :: "r"(dst), "l"(src));
}
__device__ __forceinline__ void cpa_commit() {
    asm volatile("cp.async.commit_group;");
}
template <int N>
__device__ __forceinline__ void cpa_wait() {
    asm volatile("cp.async.wait_group %0;" :: "n"(N));
}

// ============================================================
// Pre-pass A: query fp32 -> fp16
// ============================================================
__global__ void __launch_bounds__(256) conv_q(const float4* __restrict__ q)
{
    int i = blockIdx.x * 256 + threadIdx.x;
    float4 v = q[i];
    half2 lo = __floats2half2_rn(v.x, v.y);
    half2 hi = __floats2half2_rn(v.z, v.w);
    uint2 pk;
    pk.x = *(unsigned*)&lo;
    pk.y = *(unsigned*)&hi;
    ((uint2*)g_qh)[i] = pk;
}

// ============================================================
// Pre-pass B: transpose + fp16 both weights
// ============================================================
__global__ void __launch_bounds__(256) conv_w(
    const float* __restrict__ w1, const float* __restrict__ w2)
{
    int i = blockIdx.x * 256 + threadIdx.x;
    if (i < 768 * 256) {
        int n = i >> 8, k = i & 255;
        g_whq[i] = __float2half_rn(w1[k * 768 + n]);
    } else {
        int j = i - 768 * 256;
        int n = j >> 8, k = j & 255;
        g_whp[j] = __float2half_rn(w2[k * 256 + n]);
    }
}

// ============================================================
// Pre-pass C: fused bias+mask table (4 win-types x 8 heads),
// half2 words laid out exactly like the P fragment (na*4+tg).
// ============================================================
__device__ __forceinline__ int cnt_of(int type, int tok) {
    int iy = tok / 7, ix = tok - iy * 7;
    int ry = (type & 2) ? (iy < 4 ? 1 : 2) : 0;
    int rx = (type & 1) ? (ix < 4 ? 1 : 2) : 0;
    return ry * 3 + rx;
}
__global__ void __launch_bounds__(256) tbl_build(const float* __restrict__ rbt)
{
    int idx = blockIdx.x * 256 + threadIdx.x;      // < 4*8*64*36
    int w = idx % 36;
    int row = (idx / 36) & 63;
    int h = (idx / 2304) & 7;
    int type = idx / 18432;
    int na = w >> 2, tg = w & 3;
    float v[2];
#pragma unroll
    for (int e = 0; e < 2; e++) {
        int col = na * 8 + 2 * tg + e;
        float val = -60000.f;
        if (row < 49 && col < 49) {
            int iy = row / 7, ix = row - iy * 7;
            int jy = col / 7, jx = col - jy * 7;
            val = rbt[((iy - jy + 6) * 13 + (ix - jx + 6)) * 8 + h];
            if (cnt_of(type, row) != cnt_of(type, col)) val -= 100.f;
        }
        v[e] = val;
    }
    half2 p = __floats2half2_rn(v[0], v[1]);
    g_tblw[idx] = *(unsigned*)&p;
}

// ============================================================
// FP16 GEMM: block 128x128, 8 warps, K-chunk 32, 3-stage cp.async.
// ============================================================
#define A_ST 2560
#define B_BASE 7680
#define SMEM_BYTES 61440

template <int MODE>
__global__ void __launch_bounds__(256) hgemm(
    const float* __restrict__ bias, float* __restrict__ out)
{
    extern __shared__ unsigned sw[];
    __shared__ int rsrc[128];

    const int tid = threadIdx.x;
    const int m0 = blockIdx.x * 128;
    const int n0 = blockIdx.y * 128;

    if (MODE == 0 && tid < 128) {
        int m = m0 + tid;
        int win = m / 49, n = m - win * 49;
        int b = win >> 6, wy = (win >> 3) & 7, wx = win & 7;
        int iy = n / 7, ix = n - iy * 7;
        int y = wy * 7 + iy + 3; if (y >= 56) y -= 56;
        int x = wx * 7 + ix + 3; if (x >= 56) x -= 56;
        rsrc[tid] = ((b * 56 + y) * 56 + x) * 256;
    }
    __syncthreads();

    const unsigned sbase = (unsigned)__cvta_generic_to_shared(sw);
    const __half* Ah = (MODE == 0) ? g_qh : g_aoh;
    const __half* Bh = (MODE == 0) ? g_whq : g_whp;

    int ar[2], ac[2];
#pragma unroll
    for (int t = 0; t < 2; t++) {
        int id = tid + t * 256;
        ar[t] = id >> 2;  ac[t] = id & 3;
    }

#define ISSUE(STG, K0)                                                        \
    {                                                                         \
        _Pragma("unroll") for (int t = 0; t < 2; t++)                         \
            cpa16(sbase + ((STG) * A_ST + ar[t] * 20 + ac[t] * 4) * 4,        \
                  (MODE == 0) ? (Ah + rsrc[ar[t]] + (K0) + ac[t] * 8)         \
                              : (Ah + (m0 + ar[t]) * 256 + (K0) + ac[t] * 8));\
        _Pragma("unroll") for (int t = 0; t < 2; t++)                         \
            cpa16(sbase + (B_BASE + (STG) * A_ST + ar[t] * 20 + ac[t] * 4) * 4,\
                  Bh + (n0 + ar[t]) * 256 + (K0) + ac[t] * 8);                \
    }

    float acc[4][4][4];
#pragma unroll
    for (int i = 0; i < 4; i++)
#pragma unroll
        for (int j = 0; j < 4; j++)
#pragma unroll
            for (int l = 0; l < 4; l++) acc[i][j][l] = 0.f;

    const int warp = tid >> 5, lane = tid & 31;
    const int g = lane >> 2, tg = lane & 3;
    const int wm = warp >> 2, wn = warp & 3;

    ISSUE(0, 0);  cpa_commit();
    ISSUE(1, 32); cpa_commit();
    cpa_wait<1>();
    __syncthreads();

    for (int it = 0; it < 8; it++) {
        const int stg = it - (it >= 6 ? 6 : (it >= 3 ? 3 : 0));
        const unsigned* As = sw + stg * A_ST;
        const unsigned* Bs = sw + B_BASE + stg * A_ST;

#pragma unroll
        for (int ka = 0; ka < 2; ka++) {
            unsigned a[4][4], bb[4][2];
            const int kw = ka * 8;
#pragma unroll
            for (int ma = 0; ma < 4; ma++) {
                int r = wm * 64 + ma * 16 + g;
                a[ma][0] = As[r * 20 + kw + tg];
                a[ma][1] = As[(r + 8) * 20 + kw + tg];
                a[ma][2] = As[r * 20 + kw + tg + 4];
                a[ma][3] = As[(r + 8) * 20 + kw + tg + 4];
            }
#pragma unroll
            for (int na = 0; na < 4; na++) {
                int nr = wn * 32 + na * 8 + g;
                bb[na][0] = Bs[nr * 20 + kw + tg];
                bb[na][1] = Bs[nr * 20 + kw + tg + 4];
            }
#pragma unroll
            for (int ma = 0; ma < 4; ma++)
#pragma unroll
                for (int na = 0; na < 4; na++) mma16(acc[ma][na], a[ma], bb[na]);
        }

        if (it + 2 < 8) {
            int ns = it + 2; ns -= (ns >= 6 ? 6 : (ns >= 3 ? 3 : 0));
            ISSUE(ns, (it + 2) * 32);
        }
        cpa_commit();
        cpa_wait<1>();
        __syncthreads();
    }
#undef ISSUE

    const float scale = 0.17677669529663687f;
#pragma unroll
    for (int ma = 0; ma < 4; ma++) {
#pragma unroll
        for (int rr = 0; rr < 2; rr++) {
            int r = m0 + wm * 64 + ma * 16 + g + rr * 8;
            int win = r / 49, n = r - win * 49;
            int obase = 0;
            if (MODE == 1) {
                int b = win >> 6, wy = (win >> 3) & 7, wx = win & 7;
                int iy = n / 7, ix = n - iy * 7;
                int y = wy * 7 + iy + 3; if (y >= 56) y -= 56;
                int x = wx * 7 + ix + 3; if (x >= 56) x -= 56;
                obase = ((b * 56 + y) * 56 + x) * 256;
            }
#pragma unroll
            for (int na = 0; na < 4; na++) {
                int c = n0 + wn * 32 + na * 8 + tg * 2;
                float v0 = acc[ma][na][rr * 2 + 0] + bias[c];
                float v1 = acc[ma][na][rr * 2 + 1] + bias[c + 1];
                if (MODE == 0) {
                    int part = c >> 8;
                    int hh = (c >> 5) & 7, d = c & 31;
                    if (part == 0) { v0 *= scale; v1 *= scale; }
                    __half* dst = (part == 0) ? g_qa : ((part == 1) ? g_ka : g_va);
                    *(half2*)(dst + (((win << 3) + hh) * 49 + n) * 32 + d) =
                        __floats2half2_rn(v0, v1);
                } else {
                    *(float2*)(out + obase + c) = make_float2(v0, v1);
                }
            }
        }
    }
}

// ============================================================
// FP16 attention: block = (window, head), 128 threads, 4 warps.
// In-smem V transpose (R11) + fused bias+mask table softmax.
// ============================================================
__global__ void __launch_bounds__(128) attn_kernel(void)
{
    const int bx = blockIdx.x;
    const int win = bx >> 3, h = bx & 7;
    const int wy = (win >> 3) & 7, wx = win & 7;
    const int type = ((wy == 7) ? 2 : 0) | ((wx == 7) ? 1 : 0);

    __shared__ unsigned Qs[64 * 20];
    __shared__ unsigned Ks[56 * 20];
    __shared__ unsigned Vt[32 * 36];     // [d][tok64], stride 36 words
    __shared__ unsigned Pw[64 * 36];

    const int tid = threadIdx.x;
    const int warp = tid >> 5, lane = tid & 31;
    const int g = lane >> 2, tg = lane & 3;

    const int base = ((win * 8 + h) * 49) * 32;
    const __half* qp = g_qa + base;
    const __half* kp = g_ka + base;
    const __half* vp = g_va + base;

    // phase 0: zero Vt (1152 words)
    for (int i = tid; i < 1152; i += 128) Vt[i] = 0u;
    __syncthreads();

    // phase 1: loads
    for (int i = tid; i < 196; i += 128) {
        int row = i >> 2, q = i & 3;
        *(uint4*)&Qs[row * 20 + q * 4] = ((const uint4*)qp)[i];
        *(uint4*)&Ks[row * 20 + q * 4] = ((const uint4*)kp)[i];
    }
    // zero K pad rows 49-55 (keeps S cols 49-55 finite for table mask)
    if (tid < 112) Ks[980 + tid] = 0u;
    if (tid < 28)  Ks[980 + 112 + tid] = 0u;
    // V: load + transpose into Vt[d][tok] (tokens 0-48; rest stays 0)
    {
        __half* Vh = (__half*)Vt;
        for (int i = tid; i < 196; i += 128) {
            int j = i >> 2, d0 = (i & 3) * 8;
            uint4 v = ((const uint4*)vp)[i];
            __half h8[8];
            *(uint4*)h8 = v;
#pragma unroll
            for (int t = 0; t < 8; t++) Vh[(d0 + t) * 72 + j] = h8[t];
        }
    }
    __syncthreads();

    const int r0 = warp * 16 + g;
    float invs[2];
    const unsigned* tbl = g_tblw + (type * 8 + h) * 2304;

    // ---- S = Q K^T (fp16 k16), fused table bias+mask+exp+rowsum ----
    {
        float acc[7][4];
#pragma unroll
        for (int na = 0; na < 7; na++)
#pragma unroll
            for (int l = 0; l < 4; l++) acc[na][l] = 0.f;

#pragma unroll
        for (int ka = 0; ka < 2; ka++) {
            const int kw = ka * 8;
            unsigned a[4];
            a[0] = Qs[r0 * 20 + kw + tg];
            a[1] = Qs[(r0 + 8) * 20 + kw + tg];
            a[2] = Qs[r0 * 20 + kw + tg + 4];
            a[3] = Qs[(r0 + 8) * 20 + kw + tg + 4];
#pragma unroll
            for (int na = 0; na < 7; na++) {
                int nr = na * 8 + g;
                unsigned b[2] = { Ks[nr * 20 + kw + tg],
                                  Ks[nr * 20 + kw + tg + 4] };
                mma16(acc[na], a, b);
            }
        }

#pragma unroll
        for (int half = 0; half < 2; half++) {
            int row = r0 + half * 8;
            const unsigned* tbr = tbl + row * 36;
            float esum = 0.f;
#pragma unroll
            for (int na = 0; na < 7; na++) {
                unsigned tw = __ldg(tbr + na * 4 + tg);
                half2 th = *(half2*)&tw;
                float ev0 = __expf(acc[na][half * 2 + 0] + __low2float(th));
                float ev1 = __expf(acc[na][half * 2 + 1] + __high2float(th));
                half2 p = __floats2half2_rn(ev0, ev1);
                Pw[row * 36 + na * 4 + tg] = *(unsigned*)&p;
                esum += ev0 + ev1;
            }
            Pw[row * 36 + 28 + tg] = 0u;           // cols 56-63 zero
            esum += __shfl_xor_sync(0xffffffffu, esum, 1);
            esum += __shfl_xor_sync(0xffffffffu, esum, 2);
            invs[half] = 1.f / esum;
        }
    }
    __syncwarp();

    // ---- O = P V (fp16 k16, k = 64 tokens incl. zero pad) ----
    {
        float o[4][4];
#pragma unroll
        for (int na = 0; na < 4; na++)
#pragma unroll
            for (int l = 0; l < 4; l++) o[na][l] = 0.f;

#pragma unroll
        for (int ka = 0; ka < 4; ka++) {
            const int kw = ka * 8;
            unsigned a[4];
            a[0] = Pw[r0 * 36 + kw + tg];
            a[1] = Pw[(r0 + 8) * 36 + kw + tg];
            a[2] = Pw[r0 * 36 + kw + tg + 4];
            a[3] = Pw[(r0 + 8) * 36 + kw + tg + 4];
#pragma unroll
            for (int na = 0; na < 4; na++) {
                int dr = na * 8 + g;
                unsigned b[2] = { Vt[dr * 36 + kw + tg],
                                  Vt[dr * 36 + kw + tg + 4] };
                mma16(o[na], a, b);
            }
        }

#pragma unroll
        for (int half = 0; half < 2; half++) {
            int row = r0 + half * 8;
            if (row < 49) {
                float s = invs[half];
                __half* op = g_aoh + (win * 49 + row) * 256 + h * 32;
#pragma unroll
                for (int na = 0; na < 4; na++) {
                    int col = na * 8 + 2 * tg;
                    *(half2*)(op + col) =
                        __floats2half2_rn(o[na][half * 2 + 0] * s,
                                          o[na][half * 2 + 1] * s);
                }
            }
        }
    }
}

// ============================================================
extern "C" void kernel_launch(void* const* d_in, const int* in_sizes, int n_in,
                              void* d_out, int out_size)
{
    const float* query  = (const float*)d_in[0];
    const float* w_qkv  = (const float*)d_in[1];
    const float* b_qkv  = (const float*)d_in[2];
    const float* w_proj = (const float*)d_in[3];
    const float* b_proj = (const float*)d_in[4];
    const float* rbt    = (const float*)d_in[5];
    float* out = (float*)d_out;

    static int attr_done = 0;
    if (!attr_done) {
        cudaFuncSetAttribute(hgemm<0>,
            cudaFuncAttributeMaxDynamicSharedMemorySize, SMEM_BYTES);
        cudaFuncSetAttribute(hgemm<1>,
            cudaFuncAttributeMaxDynamicSharedMemorySize, SMEM_BYTES);
        attr_done = 1;
    }

    conv_q<<<12544, 256>>>((const float4*)query);
    conv_w<<<1024, 256>>>(w_qkv, w_proj);
    tbl_build<<<288, 256>>>(rbt);

    dim3 g1(392, 6);
    hgemm<0><<<g1, 256, SMEM_BYTES>>>(b_qkv, nullptr);

    attn_kernel<<<8192, 128>>>();

    dim3 g3(392, 2);
    hgemm<1><<<g3, 256, SMEM_BYTES>>>(b_proj, out);
}